// round 1
// baseline (speedup 1.0000x reference)
#include <cuda_runtime.h>

#define BB 32
#define CC 512
#define HWP 784
#define MM 200
#define NCC 50
#define NMM 4
#define KK 5

#define MT 32
#define PT 8
#define PAIRS 4
#define CT 8

// device-global scratch (no allocations allowed)
__device__ float g_cl[KK * CC];
__device__ float g_bg[BB * KK * HWP];
__device__ float g_pm[BB * MM * KK];

// ---------------------------------------------------------------------------
// 1. L1-normalize the clutter model: g_cl[k][c] = clip(cl)/max(sum_c clip,1e-12)
// ---------------------------------------------------------------------------
__global__ void cl_kernel(const float* __restrict__ clutter) {
    __shared__ float red[16];
    const int t = threadIdx.x;          // 0..511 == C
    const int lane = t & 31, w = t >> 5;
    for (int k = 0; k < KK; ++k) {
        float v = clutter[k * CC + t];
        v = fminf(fmaxf(v, 0.0f), 1.0f);
        float s = v;
        #pragma unroll
        for (int o = 16; o > 0; o >>= 1) s += __shfl_xor_sync(0xffffffffu, s, o);
        if (lane == 0) red[w] = s;
        __syncthreads();
        if (t < 16) {
            float r = red[t];
            #pragma unroll
            for (int o = 8; o > 0; o >>= 1) r += __shfl_xor_sync(0x0000ffffu, r, o);
            if (t == 0) red[0] = r;
        }
        __syncthreads();
        const float tot = red[0];
        g_cl[k * CC + t] = v / fmaxf(tot, 1e-12f);
        __syncthreads();
    }
}

// ---------------------------------------------------------------------------
// 2. Background log-likelihood: g_bg[b][k][p] = log(0.3 * sum_c x*cl + 1e-10)
// ---------------------------------------------------------------------------
__global__ void bg_kernel(const float* __restrict__ x) {
    __shared__ float cls[KK * CC];
    const int b = blockIdx.y;
    for (int i = threadIdx.x; i < KK * CC; i += blockDim.x) cls[i] = g_cl[i];
    __syncthreads();
    const int p = blockIdx.x * blockDim.x + threadIdx.x;
    if (p >= HWP) return;
    float a0 = 0.f, a1 = 0.f, a2 = 0.f, a3 = 0.f, a4 = 0.f;
    const float* xb = x + (size_t)b * CC * HWP + p;
    #pragma unroll 4
    for (int c = 0; c < CC; ++c) {
        const float xv = xb[(size_t)c * HWP];
        a0 += xv * cls[0 * CC + c];
        a1 += xv * cls[1 * CC + c];
        a2 += xv * cls[2 * CC + c];
        a3 += xv * cls[3 * CC + c];
        a4 += xv * cls[4 * CC + c];
    }
    float* o = g_bg + (size_t)b * KK * HWP + p;
    o[0 * HWP] = __logf(a0 * 0.3f + 1e-10f);
    o[1 * HWP] = __logf(a1 * 0.3f + 1e-10f);
    o[2 * HWP] = __logf(a2 * 0.3f + 1e-10f);
    o[3 * HWP] = __logf(a3 * 0.3f + 1e-10f);
    o[4 * HWP] = __logf(a4 * 0.3f + 1e-10f);
}

// ---------------------------------------------------------------------------
// 3. Zero the per-model accumulator
// ---------------------------------------------------------------------------
__global__ void zero_pm_kernel() {
    const int i = blockIdx.x * 256 + threadIdx.x;
    if (i < BB * MM * KK) g_pm[i] = 0.0f;
}

// ---------------------------------------------------------------------------
// 4. Main kernel: fused fg contraction (f32x2 packed over pixel pairs) +
//    on-the-fly L1 denominator + log + occlusion max + atomic reduction.
//    Tile: MT=32 mixtures x PT=8 pixels x all B=32, c-chunks of 8.
//    Thread tile: 4b x 4m x 1 pixel-pair  (8bg x 8mg x 4pair = 256 threads)
// ---------------------------------------------------------------------------
__global__ void __launch_bounds__(256) fg_kernel(const float* __restrict__ x,
                                                 const float* __restrict__ mix) {
    __shared__ float2 xs[CT][BB][PAIRS + 1];
    __shared__ float2 ms[CT][MT][PAIRS + 1];
    __shared__ float2 sden[MT][PAIRS];

    const int tid = threadIdx.x;
    const int ptile = blockIdx.x;        // 98 pixel tiles
    const int mbase = blockIdx.y * MT;   // 7 m tiles (last partial)

    // ---- loader role: tid<128 loads x slice, tid>=128 loads+clips mix slice
    const int lslot = tid & 127;
    const int lrow  = lslot >> 2;        // b (x) or local m (mix)
    const int lp    = lslot & 3;         // pair index
    const int lp0   = ptile * PT + lp * 2;
    const bool isx  = tid < 128;
    const int mload = mbase + lrow;
    const bool mvalid = mload < MM;

    const float* xptr = x   + ((size_t)lrow  * CC) * HWP + lp0;
    const float* mptr = mix + ((size_t)mload * CC) * HWP + lp0;

    float2 dacc = make_float2(0.0f, 0.0f);

    // ---- compute role
    const int bg    = tid & 7;
    const int mg    = (tid >> 3) & 7;
    const int pairc = tid >> 6;

    unsigned long long acc[4][4];
    #pragma unroll
    for (int i = 0; i < 4; ++i)
        #pragma unroll
        for (int j = 0; j < 4; ++j) acc[i][j] = 0ull;

    for (int it = 0; it < CC / CT; ++it) {
        __syncthreads();
        const int cb = it * CT;
        if (isx) {
            #pragma unroll
            for (int c = 0; c < CT; ++c)
                xs[c][lrow][lp] =
                    *reinterpret_cast<const float2*>(xptr + (size_t)(cb + c) * HWP);
        } else if (mvalid) {
            #pragma unroll
            for (int c = 0; c < CT; ++c) {
                float2 v =
                    *reinterpret_cast<const float2*>(mptr + (size_t)(cb + c) * HWP);
                v.x = fminf(fmaxf(v.x, 0.0f), 1.0f);
                v.y = fminf(fmaxf(v.y, 0.0f), 1.0f);
                ms[c][lrow][lp] = v;
                dacc.x += v.x;
                dacc.y += v.y;
            }
        } else {
            #pragma unroll
            for (int c = 0; c < CT; ++c) ms[c][lrow][lp] = make_float2(0.0f, 0.0f);
        }
        __syncthreads();

        #pragma unroll
        for (int c = 0; c < CT; ++c) {
            unsigned long long xv[4], mv[4];
            #pragma unroll
            for (int i = 0; i < 4; ++i)
                xv[i] = *reinterpret_cast<const unsigned long long*>(
                    &xs[c][bg * 4 + i][pairc]);
            #pragma unroll
            for (int j = 0; j < 4; ++j)
                mv[j] = *reinterpret_cast<const unsigned long long*>(
                    &ms[c][mg * 4 + j][pairc]);
            #pragma unroll
            for (int i = 0; i < 4; ++i)
                #pragma unroll
                for (int j = 0; j < 4; ++j)
                    asm("fma.rn.f32x2 %0, %1, %2, %0;"
                        : "+l"(acc[i][j])
                        : "l"(xv[i]), "l"(mv[j]));
        }
    }

    if (!isx) sden[lrow][lp] = dacc;
    __syncthreads();

    // ---- epilogue: normalize, log, occlusion-max against bg, atomic-accumulate
    const int p0 = ptile * PT + pairc * 2;
    #pragma unroll
    for (int j = 0; j < 4; ++j) {
        const int ml  = mg * 4 + j;
        const int m_g = mbase + ml;
        const float2 den = sden[ml][pairc];
        const float dx = fmaxf(den.x, 1e-12f);
        const float dy = fmaxf(den.y, 1e-12f);
        if (m_g < MM) {
            #pragma unroll
            for (int i = 0; i < 4; ++i) {
                const int b = bg * 4 + i;
                const float2 a = *reinterpret_cast<const float2*>(&acc[i][j]);
                const float f0 = __logf(__fdividef(a.x, dx) * 0.7f + 1e-10f);
                const float f1 = __logf(__fdividef(a.y, dy) * 0.7f + 1e-10f);
                const float* bgp = g_bg + (size_t)b * KK * HWP + p0;
                float* pmp = g_pm + ((size_t)b * MM + m_g) * KK;
                #pragma unroll
                for (int k = 0; k < KK; ++k) {
                    const float s = fmaxf(f0, bgp[k * HWP]) +
                                    fmaxf(f1, bgp[k * HWP + 1]);
                    atomicAdd(&pmp[k], s);
                }
            }
        }
    }
}

// ---------------------------------------------------------------------------
// 5. Final reduction: out[b][nc] = max over (nm, k) of per_model
// ---------------------------------------------------------------------------
__global__ void final_kernel(float* __restrict__ out) {
    const int idx = blockIdx.x * 256 + threadIdx.x;
    if (idx >= BB * NCC) return;
    const int b = idx / NCC, nc = idx % NCC;
    const float* p = g_pm + ((size_t)b * MM + nc * NMM) * KK;
    float m = -3.402823466e+38f;
    #pragma unroll
    for (int t = 0; t < NMM * KK; ++t) m = fmaxf(m, p[t]);
    out[idx] = m;
}

// ---------------------------------------------------------------------------
extern "C" void kernel_launch(void* const* d_in, const int* in_sizes, int n_in,
                              void* d_out, int out_size) {
    const float* x       = (const float*)d_in[0];
    const float* mix     = (const float*)d_in[1];
    const float* clutter = (const float*)d_in[2];
    float* out = (float*)d_out;

    cl_kernel<<<1, CC>>>(clutter);
    bg_kernel<<<dim3((HWP + 127) / 128, BB), 128>>>(x);
    zero_pm_kernel<<<(BB * MM * KK + 255) / 256, 256>>>();
    fg_kernel<<<dim3(HWP / PT, (MM + MT - 1) / MT), 256>>>(x, mix);
    final_kernel<<<(BB * NCC + 255) / 256, 256>>>(out);
}

// round 2
// speedup vs baseline: 1.2313x; 1.2313x over previous
#include <cuda_runtime.h>
#include <cstdint>

#define BB 32
#define CC 512
#define HWP 784
#define MM 200
#define NCC 50
#define NMM 4
#define KK 5

#define MT 32
#define PT 16
#define CT 4
#define NSTEP (CC / CT)   // 128

typedef unsigned long long ull;

__device__ float g_cl[KK * CC];
__device__ float g_bg[BB * KK * HWP];
__device__ float g_pm[BB * MM * KK];

__device__ __forceinline__ unsigned su32(const void* p) {
    return (unsigned)__cvta_generic_to_shared(p);
}
__device__ __forceinline__ void clip4(float4& v) {
    v.x = fminf(fmaxf(v.x, 0.0f), 1.0f);
    v.y = fminf(fmaxf(v.y, 0.0f), 1.0f);
    v.z = fminf(fmaxf(v.z, 0.0f), 1.0f);
    v.w = fminf(fmaxf(v.w, 0.0f), 1.0f);
}

// ---------------------------------------------------------------------------
__global__ void cl_kernel(const float* __restrict__ clutter) {
    __shared__ float red[16];
    const int t = threadIdx.x;
    const int lane = t & 31, w = t >> 5;
    for (int k = 0; k < KK; ++k) {
        float v = clutter[k * CC + t];
        v = fminf(fmaxf(v, 0.0f), 1.0f);
        float s = v;
        #pragma unroll
        for (int o = 16; o > 0; o >>= 1) s += __shfl_xor_sync(0xffffffffu, s, o);
        if (lane == 0) red[w] = s;
        __syncthreads();
        if (t < 16) {
            float r = red[t];
            #pragma unroll
            for (int o = 8; o > 0; o >>= 1) r += __shfl_xor_sync(0x0000ffffu, r, o);
            if (t == 0) red[0] = r;
        }
        __syncthreads();
        const float tot = red[0];
        g_cl[k * CC + t] = v / fmaxf(tot, 1e-12f);
        __syncthreads();
    }
}

// ---------------------------------------------------------------------------
__global__ void bg_kernel(const float* __restrict__ x) {
    __shared__ float cls[KK * CC];
    const int b = blockIdx.y;
    for (int i = threadIdx.x; i < KK * CC; i += blockDim.x) cls[i] = g_cl[i];
    __syncthreads();
    const int p = blockIdx.x * blockDim.x + threadIdx.x;
    if (p >= HWP) return;
    float a0 = 0.f, a1 = 0.f, a2 = 0.f, a3 = 0.f, a4 = 0.f;
    const float* xb = x + (size_t)b * CC * HWP + p;
    #pragma unroll 4
    for (int c = 0; c < CC; ++c) {
        const float xv = xb[(size_t)c * HWP];
        a0 += xv * cls[0 * CC + c];
        a1 += xv * cls[1 * CC + c];
        a2 += xv * cls[2 * CC + c];
        a3 += xv * cls[3 * CC + c];
        a4 += xv * cls[4 * CC + c];
    }
    float* o = g_bg + (size_t)b * KK * HWP + p;
    o[0 * HWP] = __logf(a0 * 0.3f + 1e-10f);
    o[1 * HWP] = __logf(a1 * 0.3f + 1e-10f);
    o[2 * HWP] = __logf(a2 * 0.3f + 1e-10f);
    o[3 * HWP] = __logf(a3 * 0.3f + 1e-10f);
    o[4 * HWP] = __logf(a4 * 0.3f + 1e-10f);
}

// ---------------------------------------------------------------------------
__global__ void zero_pm_kernel() {
    const int i = blockIdx.x * 256 + threadIdx.x;
    if (i < BB * MM * KK) g_pm[i] = 0.0f;
}

// ---------------------------------------------------------------------------
// fg main kernel.
//   block: 256 threads = 8bg x 8mg x 4pc ; tile 32b x 32m x 16px ; CT=4 c/step
//   smem layout per stage (float4 units): slot = (c*4 + p4)*32 + (row ^ (p4<<1))
//   x: 3-stage cp.async pipeline, m: 2-stage register->STS (clip + denom at load)
// ---------------------------------------------------------------------------
__global__ void __launch_bounds__(256, 2) fg_kernel(const float* __restrict__ x,
                                                    const float* __restrict__ mix) {
    __shared__ float4 arena[2816];         // 45 KB
    float4* xs   = arena;                  // [3][512]
    float4* msm  = arena + 1536;           // [2][512]
    float4* sden = arena + 2560;           // [2][32][4]
    float*  pm   = (float*)arena;          // overlay [32][32][5] = 5120 f

    const int tid   = threadIdx.x;
    const int mtile = blockIdx.x;          // 7  (fastest -> x L2 reuse)
    const int ptile = blockIdx.y;          // 49
    const int mbase = mtile * MT;

    // ---- loader mapping: (row, p4, c-half)
    const int lp4  = tid & 3;
    const int lrow = (tid >> 2) & 31;
    const int lc   = tid >> 7;                         // 0/1 -> c = lc, lc+2
    const int px0l = ptile * PT + lp4 * 4;
    const int lsw  = lrow ^ (lp4 << 1);
    const int slotA = (lc * 4 + lp4) * 32 + lsw;
    const int slotB = slotA + 256;                     // c + 2
    const float* xsA = x + ((size_t)lrow * CC + lc) * HWP + px0l;
    const float* xsB = xsA + 2 * HWP;
    const int mrow_g = mbase + lrow;
    const int mrow_c = mrow_g < MM ? mrow_g : MM - 1;
    const float* msA = mix + ((size_t)mrow_c * CC + lc) * HWP + px0l;
    const float* msB = msA + 2 * HWP;
    const unsigned xs_base = su32(xs);

    // ---- compute mapping
    const int bg = tid & 7;
    const int mg = (tid >> 3) & 7;
    const int pc = tid >> 6;
    int xo[4], mo[4];
    #pragma unroll
    for (int i = 0; i < 4; ++i) xo[i] = pc * 32 + ((bg + 8 * i) ^ (pc << 1));
    #pragma unroll
    for (int j = 0; j < 4; ++j) mo[j] = pc * 32 + ((mg + 8 * j) ^ (pc << 1));

    ull accl[4][4], acch[4][4];
    #pragma unroll
    for (int i = 0; i < 4; ++i)
        #pragma unroll
        for (int j = 0; j < 4; ++j) { accl[i][j] = 0ull; acch[i][j] = 0ull; }

    float4 dacc = make_float4(0.f, 0.f, 0.f, 0.f);
    float4 mra, mrb;

    // ---- prologue: x stages 0,1 via cp.async ; m stage 0 -> smem, stage 1 -> regs
    #pragma unroll
    for (int s = 0; s < 2; ++s) {
        unsigned d0 = xs_base + (unsigned)((s * 512 + slotA) * 16);
        unsigned d1 = xs_base + (unsigned)((s * 512 + slotB) * 16);
        const float* s0 = xsA + (size_t)s * CT * HWP;
        const float* s1 = xsB + (size_t)s * CT * HWP;
        asm volatile("cp.async.cg.shared.global [%0], [%1], 16;" ::"r"(d0), "l"(s0));
        asm volatile("cp.async.cg.shared.global [%0], [%1], 16;" ::"r"(d1), "l"(s1));
        asm volatile("cp.async.commit_group;");
    }
    mra = *(const float4*)(msA);
    mrb = *(const float4*)(msB);
    clip4(mra); clip4(mrb);
    msm[slotA] = mra;
    msm[slotB] = mrb;
    dacc.x += mra.x + mrb.x; dacc.y += mra.y + mrb.y;
    dacc.z += mra.z + mrb.z; dacc.w += mra.w + mrb.w;
    mra = *(const float4*)(msA + CT * HWP);
    mrb = *(const float4*)(msB + CT * HWP);
    clip4(mra); clip4(mrb);

    // ---- main pipeline
    int xbuf = 0, mbuf = 0, nbuf = 2;   // compute-x buf, compute-m buf, next-issue x buf
    for (int s = 0; s < NSTEP; ++s) {
        asm volatile("cp.async.wait_group 1;");
        __syncthreads();

        // STS m stage s+1
        {
            const int mb = ((s + 1) & 1) * 512;
            msm[mb + slotA] = mra;
            msm[mb + slotB] = mrb;
            if (s + 1 < NSTEP) {
                dacc.x += mra.x + mrb.x; dacc.y += mra.y + mrb.y;
                dacc.z += mra.z + mrb.z; dacc.w += mra.w + mrb.w;
            }
        }
        // issue x stage s+2 ; load m stage s+2 (clamped at tail)
        {
            const int nst = (s + 2 < NSTEP) ? s + 2 : NSTEP - 1;
            unsigned d0 = xs_base + (unsigned)((nbuf * 512 + slotA) * 16);
            unsigned d1 = xs_base + (unsigned)((nbuf * 512 + slotB) * 16);
            const float* s0 = xsA + (size_t)nst * CT * HWP;
            const float* s1 = xsB + (size_t)nst * CT * HWP;
            asm volatile("cp.async.cg.shared.global [%0], [%1], 16;" ::"r"(d0), "l"(s0));
            asm volatile("cp.async.cg.shared.global [%0], [%1], 16;" ::"r"(d1), "l"(s1));
            asm volatile("cp.async.commit_group;");
            mra = *(const float4*)(msA + (size_t)nst * CT * HWP);
            mrb = *(const float4*)(msB + (size_t)nst * CT * HWP);
            clip4(mra); clip4(mrb);
        }

        // compute stage s
        {
            const float4* xb = xs + xbuf * 512;
            const float4* mb = msm + mbuf * 512;
            #pragma unroll
            for (int c = 0; c < CT; ++c) {
                ulonglong2 xv[4], mv[4];
                #pragma unroll
                for (int i = 0; i < 4; ++i)
                    xv[i] = *(const ulonglong2*)(xb + c * 128 + xo[i]);
                #pragma unroll
                for (int j = 0; j < 4; ++j)
                    mv[j] = *(const ulonglong2*)(mb + c * 128 + mo[j]);
                #pragma unroll
                for (int i = 0; i < 4; ++i)
                    #pragma unroll
                    for (int j = 0; j < 4; ++j) {
                        asm("fma.rn.f32x2 %0, %1, %2, %0;"
                            : "+l"(accl[i][j]) : "l"(xv[i].x), "l"(mv[j].x));
                        asm("fma.rn.f32x2 %0, %1, %2, %0;"
                            : "+l"(acch[i][j]) : "l"(xv[i].y), "l"(mv[j].y));
                    }
            }
        }
        if (++xbuf == 3) xbuf = 0;
        if (++nbuf == 3) nbuf = 0;
        mbuf ^= 1;
    }

    // ---- denominator -> smem
    sden[lc * 128 + lrow * 4 + lp4] = dacc;
    __syncthreads();

    // ---- zero pm tile (overlays xs, safe after bar)
    for (int q = tid; q < BB * MT * KK; q += 256) pm[q] = 0.0f;
    __syncthreads();

    // ---- epilogue: normalize, log, occlusion-max vs bg, smem accumulate
    const int px0c = ptile * PT + pc * 4;
    #pragma unroll
    for (int i = 0; i < 4; ++i) {
        const int b = bg + 8 * i;
        float fl[4][4];
        #pragma unroll
        for (int j = 0; j < 4; ++j) {
            const int mloc = mg + 8 * j;
            const float4 d0 = sden[0 * 128 + mloc * 4 + pc];
            const float4 d1 = sden[1 * 128 + mloc * 4 + pc];
            const float dx = fmaxf(d0.x + d1.x, 1e-12f);
            const float dy = fmaxf(d0.y + d1.y, 1e-12f);
            const float dz = fmaxf(d0.z + d1.z, 1e-12f);
            const float dw = fmaxf(d0.w + d1.w, 1e-12f);
            const float2 al = *(const float2*)&accl[i][j];
            const float2 ah = *(const float2*)&acch[i][j];
            fl[j][0] = __logf(__fdividef(al.x, dx) * 0.7f + 1e-10f);
            fl[j][1] = __logf(__fdividef(al.y, dy) * 0.7f + 1e-10f);
            fl[j][2] = __logf(__fdividef(ah.x, dz) * 0.7f + 1e-10f);
            fl[j][3] = __logf(__fdividef(ah.y, dw) * 0.7f + 1e-10f);
        }
        const float* bgp = g_bg + (size_t)b * KK * HWP + px0c;
        #pragma unroll
        for (int k = 0; k < KK; ++k) {
            const float4 b4 = *(const float4*)(bgp + k * HWP);
            #pragma unroll
            for (int j = 0; j < 4; ++j) {
                const float s = fmaxf(fl[j][0], b4.x) + fmaxf(fl[j][1], b4.y) +
                                fmaxf(fl[j][2], b4.z) + fmaxf(fl[j][3], b4.w);
                atomicAdd(&pm[(b * MT + mg + 8 * j) * KK + k], s);
            }
        }
    }
    __syncthreads();

    // ---- flush pm tile to global
    for (int q = tid; q < BB * MT * KK; q += 256) {
        const int k = q % KK;
        const int t = q / KK;
        const int mloc = t % MT;
        const int b = t / MT;
        const int m_g = mbase + mloc;
        if (m_g < MM)
            atomicAdd(&g_pm[((size_t)b * MM + m_g) * KK + k], pm[q]);
    }
}

// ---------------------------------------------------------------------------
__global__ void final_kernel(float* __restrict__ out) {
    const int idx = blockIdx.x * 256 + threadIdx.x;
    if (idx >= BB * NCC) return;
    const int b = idx / NCC, nc = idx % NCC;
    const float* p = g_pm + ((size_t)b * MM + nc * NMM) * KK;
    float m = -3.402823466e+38f;
    #pragma unroll
    for (int t = 0; t < NMM * KK; ++t) m = fmaxf(m, p[t]);
    out[idx] = m;
}

// ---------------------------------------------------------------------------
extern "C" void kernel_launch(void* const* d_in, const int* in_sizes, int n_in,
                              void* d_out, int out_size) {
    const float* x       = (const float*)d_in[0];
    const float* mix     = (const float*)d_in[1];
    const float* clutter = (const float*)d_in[2];
    float* out = (float*)d_out;

    cl_kernel<<<1, CC>>>(clutter);
    bg_kernel<<<dim3((HWP + 127) / 128, BB), 128>>>(x);
    zero_pm_kernel<<<(BB * MM * KK + 255) / 256, 256>>>();
    fg_kernel<<<dim3((MM + MT - 1) / MT, HWP / PT), 256>>>(x, mix);
    final_kernel<<<(BB * NCC + 255) / 256, 256>>>(out);
}